// round 5
// baseline (speedup 1.0000x reference)
#include <cuda_runtime.h>
#include <cstddef>
#include <cstring>

#define N_NODES 50000
#define N_EDGES 800000
#define IN_C 128
#define HID_C 128
#define OUT_C 64
#define CSR_BLOCKS 148
#define CSR_THREADS 1024
#define CSR_CHUNK 338          // 148*338 = 50024 >= N_NODES

typedef unsigned long long u64;

// ---------------- scratch (device globals: allocation-free rule) ----------------
__device__ int      g_cnt [N_NODES];
__device__ int      g_btot[CSR_BLOCKS];
__device__ int      g_rowptr[N_NODES + 1];
__device__ int      g_wp  [N_NODES];
__device__ u64      g_edge[N_EDGES];                    // packed (src, w)
__device__ unsigned g_bar;                              // monotonic grid-barrier ticket
__device__ __align__(16) float g_y1[N_NODES * HID_C];   // x @ W_l1^T
__device__ __align__(16) float g_r1[N_NODES * HID_C];   // x @ W_r1^T
__device__ __align__(16) float g_h [N_NODES * HID_C];   // layer-1 output
__device__ __align__(16) float g_y2[N_NODES * OUT_C];   // h @ W_l2^T
__device__ __align__(16) float g_r2[N_NODES * OUT_C];   // h @ W_r2^T

// ---------------- grid barrier (monotonic ticket: replay-safe, no reset) ---------
__device__ __forceinline__ void grid_bar() {
    __shared__ unsigned target;
    __syncthreads();
    if (threadIdx.x == 0) {
        __threadfence();
        unsigned t = atomicAdd(&g_bar, 1u);
        target = (t / CSR_BLOCKS + 1u) * CSR_BLOCKS;
        while (atomicAdd(&g_bar, 0u) < target) { }
        __threadfence();
    }
    __syncthreads();
}

// ---------------- single-launch CSR build (zero + hist + scan + scatter) ---------
__global__ void __launch_bounds__(CSR_THREADS)
csr_kernel(const int* __restrict__ src, const int* __restrict__ dst,
           const float* __restrict__ ew) {
    const int t = threadIdx.x;
    const int b = blockIdx.x;
    const int gt = b * CSR_THREADS + t;
    const int G = CSR_BLOCKS * CSR_THREADS;
    const int lane = t & 31;
    const int wid = t >> 5;
    __shared__ int wsum[32];
    __shared__ int s_boff;

    // --- phase 0: zero counts ---
    for (int i = gt; i < N_NODES; i += G) g_cnt[i] = 0;
    grid_bar();

    // --- phase 1: histogram of dst ---
    for (int e = gt; e < N_EDGES; e += G) atomicAdd(&g_cnt[dst[e]], 1);
    grid_bar();

    // --- phase 2: scan. block b owns nodes [b*CSR_CHUNK, ...) ---
    const int base = b * CSR_CHUNK;
    const int node = base + t;
    int v = 0;
    if (t < CSR_CHUNK && node < N_NODES) v = __ldcg(&g_cnt[node]);

    int inc = v;
#pragma unroll
    for (int off = 1; off < 32; off <<= 1) {
        int u = __shfl_up_sync(0xffffffffu, inc, off);
        if (lane >= off) inc += u;
    }
    if (lane == 31) wsum[wid] = inc;
    __syncthreads();
    if (wid == 0) {
        int wv = wsum[lane];
        int wi = wv;
#pragma unroll
        for (int off = 1; off < 32; off <<= 1) {
            int u = __shfl_up_sync(0xffffffffu, wi, off);
            if (lane >= off) wi += u;
        }
        wsum[lane] = wi;
    }
    __syncthreads();
    int ex = inc - v + ((wid > 0) ? wsum[wid - 1] : 0);
    int btot = wsum[31];
    if (t == 0) g_btot[b] = btot;
    __threadfence();
    grid_bar();

    {
        int contrib = (t < b) ? __ldcg(&g_btot[t]) : 0;
        int r = contrib;
#pragma unroll
        for (int off = 16; off > 0; off >>= 1) r += __shfl_down_sync(0xffffffffu, r, off);
        if (lane == 0) wsum[wid] = r;
        __syncthreads();
        if (wid == 0) {
            int r2 = wsum[lane];
#pragma unroll
            for (int off = 16; off > 0; off >>= 1) r2 += __shfl_down_sync(0xffffffffu, r2, off);
            if (lane == 0) s_boff = r2;
        }
        __syncthreads();
    }
    if (t < CSR_CHUNK && node < N_NODES) {
        int rp = s_boff + ex;
        g_rowptr[node] = rp;
        g_wp[node] = rp;
    }
    if (b == 0 && t == 0) g_rowptr[N_NODES] = N_EDGES;
    __threadfence();
    grid_bar();

    // --- phase 3: scatter packed (src, w) records ---
    for (int e = gt; e < N_EDGES; e += G) {
        int d = dst[e];
        int pos = atomicAdd(&g_wp[d], 1);
        u64 rec = ((u64)__float_as_uint(ew[e]) << 32) | (unsigned)src[e];
        g_edge[pos] = rec;
    }
}

// ---------------- gather aggregation + fused SAGE epilogue ------------------------
__device__ __forceinline__ void unpack_edge(u64 rec, int& s, float& w) {
    s = (int)(unsigned)rec;
    w = __uint_as_float((unsigned)(rec >> 32));
}

template <bool RELU>
__global__ void __launch_bounds__(256)
gather128_kernel(const float* __restrict__ y, const float* __restrict__ r,
                 const float* __restrict__ bias, float* __restrict__ out) {
    int gt = blockIdx.x * blockDim.x + threadIdx.x;
    int node = gt >> 5;
    if (node >= N_NODES) return;
    int lane = threadIdx.x & 31;

    int beg = g_rowptr[node];
    int end = g_rowptr[node + 1];

    float ax = 0.f, ay = 0.f, az = 0.f, aw = 0.f;
    int i = beg;
    for (; i + 4 <= end; i += 4) {
        int s0, s1, s2, s3; float w0, w1, w2, w3;
        unpack_edge(g_edge[i],   s0, w0);
        unpack_edge(g_edge[i+1], s1, w1);
        unpack_edge(g_edge[i+2], s2, w2);
        unpack_edge(g_edge[i+3], s3, w3);
        float4 v0 = *reinterpret_cast<const float4*>(y + (size_t)s0 * 128 + lane * 4);
        float4 v1 = *reinterpret_cast<const float4*>(y + (size_t)s1 * 128 + lane * 4);
        float4 v2 = *reinterpret_cast<const float4*>(y + (size_t)s2 * 128 + lane * 4);
        float4 v3 = *reinterpret_cast<const float4*>(y + (size_t)s3 * 128 + lane * 4);
        ax += w0*v0.x + w1*v1.x + w2*v2.x + w3*v3.x;
        ay += w0*v0.y + w1*v1.y + w2*v2.y + w3*v3.y;
        az += w0*v0.z + w1*v1.z + w2*v2.z + w3*v3.z;
        aw += w0*v0.w + w1*v1.w + w2*v2.w + w3*v3.w;
    }
    for (; i < end; i++) {
        int s; float w;
        unpack_edge(g_edge[i], s, w);
        float4 v = *reinterpret_cast<const float4*>(y + (size_t)s * 128 + lane * 4);
        ax += w*v.x; ay += w*v.y; az += w*v.z; aw += w*v.w;
    }

    float invd = 1.0f / fmaxf((float)(end - beg), 1.0f);
    float4 r4 = *reinterpret_cast<const float4*>(r + (size_t)node * 128 + lane * 4);
    float4 b4 = *reinterpret_cast<const float4*>(bias + lane * 4);
    float4 o;
    o.x = ax * invd + b4.x + r4.x;
    o.y = ay * invd + b4.y + r4.y;
    o.z = az * invd + b4.z + r4.z;
    o.w = aw * invd + b4.w + r4.w;
    if (RELU) {
        o.x = fmaxf(o.x, 0.f); o.y = fmaxf(o.y, 0.f);
        o.z = fmaxf(o.z, 0.f); o.w = fmaxf(o.w, 0.f);
    }
    *reinterpret_cast<float4*>(out + (size_t)node * 128 + lane * 4) = o;
}

template <bool RELU>
__global__ void __launch_bounds__(256)
gather64_kernel(const float* __restrict__ y, const float* __restrict__ r,
                const float* __restrict__ bias, float* __restrict__ out) {
    int gt = blockIdx.x * blockDim.x + threadIdx.x;
    int node = gt >> 4;
    if (node >= N_NODES) return;
    int lane = threadIdx.x & 15;

    int beg = g_rowptr[node];
    int end = g_rowptr[node + 1];

    float ax = 0.f, ay = 0.f, az = 0.f, aw = 0.f;
    int i = beg;
    for (; i + 4 <= end; i += 4) {
        int s0, s1, s2, s3; float w0, w1, w2, w3;
        unpack_edge(g_edge[i],   s0, w0);
        unpack_edge(g_edge[i+1], s1, w1);
        unpack_edge(g_edge[i+2], s2, w2);
        unpack_edge(g_edge[i+3], s3, w3);
        float4 v0 = *reinterpret_cast<const float4*>(y + (size_t)s0 * 64 + lane * 4);
        float4 v1 = *reinterpret_cast<const float4*>(y + (size_t)s1 * 64 + lane * 4);
        float4 v2 = *reinterpret_cast<const float4*>(y + (size_t)s2 * 64 + lane * 4);
        float4 v3 = *reinterpret_cast<const float4*>(y + (size_t)s3 * 64 + lane * 4);
        ax += w0*v0.x + w1*v1.x + w2*v2.x + w3*v3.x;
        ay += w0*v0.y + w1*v1.y + w2*v2.y + w3*v3.y;
        az += w0*v0.z + w1*v1.z + w2*v2.z + w3*v3.z;
        aw += w0*v0.w + w1*v1.w + w2*v2.w + w3*v3.w;
    }
    for (; i < end; i++) {
        int s; float w;
        unpack_edge(g_edge[i], s, w);
        float4 v = *reinterpret_cast<const float4*>(y + (size_t)s * 64 + lane * 4);
        ax += w*v.x; ay += w*v.y; az += w*v.z; aw += w*v.w;
    }

    float invd = 1.0f / fmaxf((float)(end - beg), 1.0f);
    float4 r4 = *reinterpret_cast<const float4*>(r + (size_t)node * 64 + lane * 4);
    float4 b4 = *reinterpret_cast<const float4*>(bias + lane * 4);
    float4 o;
    o.x = ax * invd + b4.x + r4.x;
    o.y = ay * invd + b4.y + r4.y;
    o.z = az * invd + b4.z + r4.z;
    o.w = aw * invd + b4.w + r4.w;
    if (RELU) {
        o.x = fmaxf(o.x, 0.f); o.y = fmaxf(o.y, 0.f);
        o.z = fmaxf(o.z, 0.f); o.w = fmaxf(o.w, 0.f);
    }
    *reinterpret_cast<float4*>(out + (size_t)node * 64 + lane * 4) = o;
}

// ---------------- f32x2 packed-FMA GEMM, 8x16 per thread, double-buffered --------
// Virtual weight matrix = [W0; W1] stacked. BM=128 x 128 virtual cols per block.
// 128 threads, 8 rows x 16 cols per thread as 8 x 8 f32x2 accumulators. KC=8.

#define FMA2(d, a, b) asm("fma.rn.f32x2 %0, %1, %2, %0;" : "+l"(d) : "l"(a), "l"(b))

__device__ __forceinline__ float2 u64_as_f2(u64 v) {
    float2 f;
    memcpy(&f, &v, 8);
    return f;
}

__global__ void __launch_bounds__(128, 2)
gemm2x_kernel(const float* __restrict__ A,
              const float* __restrict__ W0, const float* __restrict__ W1,
              float* __restrict__ out0, float* __restrict__ out1,
              int split, int n) {
    constexpr int BM = 128, K = 128, KC = 8;
    constexpr int NCHUNK = K / KC;     // 16
    constexpr int APAD = 2 * BM + 4;   // 260 floats per k-row (duplicated A)
    constexpr int WPAD = 128 + 4;      // 132 floats per k-row

    __shared__ __align__(16) float As[2][KC][APAD];
    __shared__ __align__(16) float Ws[2][KC][WPAD];

    int row0 = blockIdx.x * BM;
    int col0 = blockIdx.y * 128;
    int tid = threadIdx.x;
    int tx = tid & 7;                  // column group: cols 16*tx .. +15
    int ty = tid >> 3;                 // row group (0..15): rows 8*ty .. +7

    // per-thread load coordinates: this thread stages row `tid` of A and
    // virtual-col `tid` of W, 8 k-values (2 float4) per chunk.
    const float* Arow = A + (size_t)(row0 + tid) * K;
    bool a_ok = (row0 + tid) < n;
    int vc = col0 + tid;
    const float* Wrow = (vc < split) ? (W0 + (size_t)vc * K)
                                     : (W1 + (size_t)(vc - split) * K);

    u64 acc[8][8];
#pragma unroll
    for (int i = 0; i < 8; i++)
#pragma unroll
        for (int j = 0; j < 8; j++) acc[i][j] = 0ull;

    float4 va0, va1, vw0, vw1;
    va0 = a_ok ? *reinterpret_cast<const float4*>(Arow + 0) : make_float4(0.f, 0.f, 0.f, 0.f);
    va1 = a_ok ? *reinterpret_cast<const float4*>(Arow + 4) : make_float4(0.f, 0.f, 0.f, 0.f);
    vw0 = *reinterpret_cast<const float4*>(Wrow + 0);
    vw1 = *reinterpret_cast<const float4*>(Wrow + 4);
    {
        float av[8] = {va0.x, va0.y, va0.z, va0.w, va1.x, va1.y, va1.z, va1.w};
        float wv[8] = {vw0.x, vw0.y, vw0.z, vw0.w, vw1.x, vw1.y, vw1.z, vw1.w};
#pragma unroll
        for (int k = 0; k < KC; k++) {
            *reinterpret_cast<float2*>(&As[0][k][2 * tid]) = make_float2(av[k], av[k]);
            Ws[0][k][tid] = wv[k];
        }
    }
    __syncthreads();

#pragma unroll
    for (int kc = 0; kc < NCHUNK; kc++) {
        int cur = kc & 1;
        // prefetch next chunk (LDG in flight during compute)
        if (kc < NCHUNK - 1) {
            int ko = (kc + 1) * KC;
            va0 = a_ok ? *reinterpret_cast<const float4*>(Arow + ko + 0) : make_float4(0.f, 0.f, 0.f, 0.f);
            va1 = a_ok ? *reinterpret_cast<const float4*>(Arow + ko + 4) : make_float4(0.f, 0.f, 0.f, 0.f);
            vw0 = *reinterpret_cast<const float4*>(Wrow + ko + 0);
            vw1 = *reinterpret_cast<const float4*>(Wrow + ko + 4);
        }
        // compute current chunk
#pragma unroll
        for (int k = 0; k < KC; k++) {
            // A: 8 duplicated pairs (rows 8ty..8ty+7), addr depends only on ty
            const ulonglong2* au = reinterpret_cast<const ulonglong2*>(&As[cur][k][16 * ty]);
            ulonglong2 a01 = au[0];
            ulonglong2 a23 = au[1];
            ulonglong2 a45 = au[2];
            ulonglong2 a67 = au[3];
            u64 ad[8] = {a01.x, a01.y, a23.x, a23.y, a45.x, a45.y, a67.x, a67.y};
            // B: 8 natural pairs (cols 16tx..16tx+15), addr depends only on tx
            const ulonglong2* bu = reinterpret_cast<const ulonglong2*>(&Ws[cur][k][16 * tx]);
            ulonglong2 b01 = bu[0];
            ulonglong2 b23 = bu[1];
            ulonglong2 b45 = bu[2];
            ulonglong2 b67 = bu[3];
            u64 bp[8] = {b01.x, b01.y, b23.x, b23.y, b45.x, b45.y, b67.x, b67.y};
#pragma unroll
            for (int i = 0; i < 8; i++) {
#pragma unroll
                for (int j = 0; j < 8; j++)
                    FMA2(acc[i][j], ad[i], bp[j]);
            }
        }
        // stage next chunk into the other buffer
        if (kc < NCHUNK - 1) {
            int nxt = cur ^ 1;
            float av[8] = {va0.x, va0.y, va0.z, va0.w, va1.x, va1.y, va1.z, va1.w};
            float wv[8] = {vw0.x, vw0.y, vw0.z, vw0.w, vw1.x, vw1.y, vw1.z, vw1.w};
#pragma unroll
            for (int k = 0; k < KC; k++) {
                *reinterpret_cast<float2*>(&As[nxt][k][2 * tid]) = make_float2(av[k], av[k]);
                Ws[nxt][k][tid] = wv[k];
            }
            __syncthreads();
        }
    }

    // ---- writeback: 16 contiguous cols per row (4 float4), 8 rows ----
    int vcBase = col0 + 16 * tx;       // 16-col group never straddles the split (splits at 64/128)
    float* base = (vcBase < split) ? (out0 + vcBase) : (out1 + (vcBase - split));
#pragma unroll
    for (int i = 0; i < 8; i++) {
        int r = row0 + ty * 8 + i;
        if (r >= n) continue;
        float* orow = base + (size_t)r * split;
#pragma unroll
        for (int q = 0; q < 4; q++) {
            float2 lo = u64_as_f2(acc[i][2 * q + 0]);
            float2 hi = u64_as_f2(acc[i][2 * q + 1]);
            *reinterpret_cast<float4*>(orow + 4 * q) = make_float4(lo.x, lo.y, hi.x, hi.y);
        }
    }
}

// ---------------- launch ----------------------------------------------------------
extern "C" void kernel_launch(void* const* d_in, const int* in_sizes, int n_in,
                              void* d_out, int out_size) {
    const float* x    = (const float*)d_in[0];
    const int*   ei   = (const int*)  d_in[1];
    const float* ew   = (const float*)d_in[2];
    // d_in[3] = node_type (unused by the reference)
    const float* W_l1 = (const float*)d_in[4];
    const float* b_l1 = (const float*)d_in[5];
    const float* W_r1 = (const float*)d_in[6];
    const float* W_l2 = (const float*)d_in[7];
    const float* b_l2 = (const float*)d_in[8];
    const float* W_r2 = (const float*)d_in[9];
    float* out = (float*)d_out;

    const int* src = ei;
    const int* dst = ei + N_EDGES;

    float *y1, *r1, *h, *y2, *r2;
    cudaGetSymbolAddress((void**)&y1, g_y1);
    cudaGetSymbolAddress((void**)&r1, g_r1);
    cudaGetSymbolAddress((void**)&h,  g_h);
    cudaGetSymbolAddress((void**)&y2, g_y2);
    cudaGetSymbolAddress((void**)&r2, g_r2);

    const int GB = (N_NODES + 127) / 128;           // 391

    // --- CSR build: ONE launch (zero + hist + scan + scatter, grid barrier) ---
    csr_kernel<<<CSR_BLOCKS, CSR_THREADS>>>(src, dst, ew);

    // --- layer 1: [W_l1; W_r1] stacked GEMM, gather-mean + fused epilogue ---
    gemm2x_kernel<<<dim3(GB, 2), 128>>>(x, W_l1, W_r1, y1, r1, 128, N_NODES);
    gather128_kernel<true><<<(N_NODES * 32 + 255) / 256, 256>>>(y1, r1, b_l1, h);

    // --- layer 2: [W_l2; W_r2] stacked GEMM (project to 64 before aggregating) ---
    gemm2x_kernel<<<dim3(GB, 1), 128>>>(h, W_l2, W_r2, y2, r2, 64, N_NODES);
    gather64_kernel<false><<<(N_NODES * 16 + 255) / 256, 256>>>(y2, r2, b_l2, out);
}

// round 6
// speedup vs baseline: 1.7406x; 1.7406x over previous
#include <cuda_runtime.h>
#include <cstddef>
#include <cstring>

#define N_NODES 50000
#define N_EDGES 800000
#define IN_C 128
#define HID_C 128
#define OUT_C 64
#define CSR_BLOCKS 148
#define CSR_THREADS 1024
#define CSR_CHUNK 338          // 148*338 = 50024 >= N_NODES

typedef unsigned long long u64;

// ---------------- scratch (device globals: allocation-free rule) ----------------
__device__ int      g_cnt [N_NODES];
__device__ int      g_btot[CSR_BLOCKS];
__device__ int      g_rowptr[N_NODES + 1];
__device__ int      g_wp  [N_NODES];
__device__ u64      g_edge[N_EDGES];                    // packed (src, w)
__device__ unsigned g_bar;                              // monotonic grid-barrier ticket
__device__ __align__(16) float g_y1[N_NODES * HID_C];   // x @ W_l1^T
__device__ __align__(16) float g_r1[N_NODES * HID_C];   // x @ W_r1^T
__device__ __align__(16) float g_h [N_NODES * HID_C];   // layer-1 output
__device__ __align__(16) float g_y2[N_NODES * OUT_C];   // h @ W_l2^T
__device__ __align__(16) float g_r2[N_NODES * OUT_C];   // h @ W_r2^T

// ---------------- grid barrier (monotonic ticket: replay-safe, no reset) ---------
__device__ __forceinline__ void grid_bar() {
    __shared__ unsigned target;
    __syncthreads();
    if (threadIdx.x == 0) {
        __threadfence();
        unsigned t = atomicAdd(&g_bar, 1u);
        target = (t / CSR_BLOCKS + 1u) * CSR_BLOCKS;
        while (atomicAdd(&g_bar, 0u) < target) { }
        __threadfence();
    }
    __syncthreads();
}

// ---------------- single-launch CSR build (zero + hist + scan + scatter) ---------
__global__ void __launch_bounds__(CSR_THREADS)
csr_kernel(const int* __restrict__ src, const int* __restrict__ dst,
           const float* __restrict__ ew) {
    const int t = threadIdx.x;
    const int b = blockIdx.x;
    const int gt = b * CSR_THREADS + t;
    const int G = CSR_BLOCKS * CSR_THREADS;
    const int lane = t & 31;
    const int wid = t >> 5;
    __shared__ int wsum[32];
    __shared__ int s_boff;

    // --- phase 0: zero counts ---
    for (int i = gt; i < N_NODES; i += G) g_cnt[i] = 0;
    grid_bar();

    // --- phase 1: histogram of dst ---
    for (int e = gt; e < N_EDGES; e += G) atomicAdd(&g_cnt[dst[e]], 1);
    grid_bar();

    // --- phase 2: scan. block b owns nodes [b*CSR_CHUNK, ...) ---
    const int base = b * CSR_CHUNK;
    const int node = base + t;
    int v = 0;
    if (t < CSR_CHUNK && node < N_NODES) v = __ldcg(&g_cnt[node]);

    int inc = v;
#pragma unroll
    for (int off = 1; off < 32; off <<= 1) {
        int u = __shfl_up_sync(0xffffffffu, inc, off);
        if (lane >= off) inc += u;
    }
    if (lane == 31) wsum[wid] = inc;
    __syncthreads();
    if (wid == 0) {
        int wv = wsum[lane];
        int wi = wv;
#pragma unroll
        for (int off = 1; off < 32; off <<= 1) {
            int u = __shfl_up_sync(0xffffffffu, wi, off);
            if (lane >= off) wi += u;
        }
        wsum[lane] = wi;
    }
    __syncthreads();
    int ex = inc - v + ((wid > 0) ? wsum[wid - 1] : 0);
    int btot = wsum[31];
    if (t == 0) g_btot[b] = btot;
    __threadfence();
    grid_bar();

    {
        int contrib = (t < b) ? __ldcg(&g_btot[t]) : 0;
        int r = contrib;
#pragma unroll
        for (int off = 16; off > 0; off >>= 1) r += __shfl_down_sync(0xffffffffu, r, off);
        if (lane == 0) wsum[wid] = r;
        __syncthreads();
        if (wid == 0) {
            int r2 = wsum[lane];
#pragma unroll
            for (int off = 16; off > 0; off >>= 1) r2 += __shfl_down_sync(0xffffffffu, r2, off);
            if (lane == 0) s_boff = r2;
        }
        __syncthreads();
    }
    if (t < CSR_CHUNK && node < N_NODES) {
        int rp = s_boff + ex;
        g_rowptr[node] = rp;
        g_wp[node] = rp;
    }
    if (b == 0 && t == 0) g_rowptr[N_NODES] = N_EDGES;
    __threadfence();
    grid_bar();

    // --- phase 3: scatter packed (src, w) records ---
    for (int e = gt; e < N_EDGES; e += G) {
        int d = dst[e];
        int pos = atomicAdd(&g_wp[d], 1);
        u64 rec = ((u64)__float_as_uint(ew[e]) << 32) | (unsigned)src[e];
        g_edge[pos] = rec;
    }
}

// ---------------- gather aggregation + fused SAGE epilogue ------------------------
__device__ __forceinline__ void unpack_edge(u64 rec, int& s, float& w) {
    s = (int)(unsigned)rec;
    w = __uint_as_float((unsigned)(rec >> 32));
}

template <bool RELU>
__global__ void __launch_bounds__(256)
gather128_kernel(const float* __restrict__ y, const float* __restrict__ r,
                 const float* __restrict__ bias, float* __restrict__ out) {
    int gt = blockIdx.x * blockDim.x + threadIdx.x;
    int node = gt >> 5;
    if (node >= N_NODES) return;
    int lane = threadIdx.x & 31;

    int beg = g_rowptr[node];
    int end = g_rowptr[node + 1];

    float ax = 0.f, ay = 0.f, az = 0.f, aw = 0.f;
    int i = beg;
    for (; i + 4 <= end; i += 4) {
        int s0, s1, s2, s3; float w0, w1, w2, w3;
        unpack_edge(g_edge[i],   s0, w0);
        unpack_edge(g_edge[i+1], s1, w1);
        unpack_edge(g_edge[i+2], s2, w2);
        unpack_edge(g_edge[i+3], s3, w3);
        float4 v0 = *reinterpret_cast<const float4*>(y + (size_t)s0 * 128 + lane * 4);
        float4 v1 = *reinterpret_cast<const float4*>(y + (size_t)s1 * 128 + lane * 4);
        float4 v2 = *reinterpret_cast<const float4*>(y + (size_t)s2 * 128 + lane * 4);
        float4 v3 = *reinterpret_cast<const float4*>(y + (size_t)s3 * 128 + lane * 4);
        ax += w0*v0.x + w1*v1.x + w2*v2.x + w3*v3.x;
        ay += w0*v0.y + w1*v1.y + w2*v2.y + w3*v3.y;
        az += w0*v0.z + w1*v1.z + w2*v2.z + w3*v3.z;
        aw += w0*v0.w + w1*v1.w + w2*v2.w + w3*v3.w;
    }
    for (; i < end; i++) {
        int s; float w;
        unpack_edge(g_edge[i], s, w);
        float4 v = *reinterpret_cast<const float4*>(y + (size_t)s * 128 + lane * 4);
        ax += w*v.x; ay += w*v.y; az += w*v.z; aw += w*v.w;
    }

    float invd = 1.0f / fmaxf((float)(end - beg), 1.0f);
    float4 r4 = *reinterpret_cast<const float4*>(r + (size_t)node * 128 + lane * 4);
    float4 b4 = *reinterpret_cast<const float4*>(bias + lane * 4);
    float4 o;
    o.x = ax * invd + b4.x + r4.x;
    o.y = ay * invd + b4.y + r4.y;
    o.z = az * invd + b4.z + r4.z;
    o.w = aw * invd + b4.w + r4.w;
    if (RELU) {
        o.x = fmaxf(o.x, 0.f); o.y = fmaxf(o.y, 0.f);
        o.z = fmaxf(o.z, 0.f); o.w = fmaxf(o.w, 0.f);
    }
    *reinterpret_cast<float4*>(out + (size_t)node * 128 + lane * 4) = o;
}

template <bool RELU>
__global__ void __launch_bounds__(256)
gather64_kernel(const float* __restrict__ y, const float* __restrict__ r,
                const float* __restrict__ bias, float* __restrict__ out) {
    int gt = blockIdx.x * blockDim.x + threadIdx.x;
    int node = gt >> 4;
    if (node >= N_NODES) return;
    int lane = threadIdx.x & 15;

    int beg = g_rowptr[node];
    int end = g_rowptr[node + 1];

    float ax = 0.f, ay = 0.f, az = 0.f, aw = 0.f;
    int i = beg;
    for (; i + 4 <= end; i += 4) {
        int s0, s1, s2, s3; float w0, w1, w2, w3;
        unpack_edge(g_edge[i],   s0, w0);
        unpack_edge(g_edge[i+1], s1, w1);
        unpack_edge(g_edge[i+2], s2, w2);
        unpack_edge(g_edge[i+3], s3, w3);
        float4 v0 = *reinterpret_cast<const float4*>(y + (size_t)s0 * 64 + lane * 4);
        float4 v1 = *reinterpret_cast<const float4*>(y + (size_t)s1 * 64 + lane * 4);
        float4 v2 = *reinterpret_cast<const float4*>(y + (size_t)s2 * 64 + lane * 4);
        float4 v3 = *reinterpret_cast<const float4*>(y + (size_t)s3 * 64 + lane * 4);
        ax += w0*v0.x + w1*v1.x + w2*v2.x + w3*v3.x;
        ay += w0*v0.y + w1*v1.y + w2*v2.y + w3*v3.y;
        az += w0*v0.z + w1*v1.z + w2*v2.z + w3*v3.z;
        aw += w0*v0.w + w1*v1.w + w2*v2.w + w3*v3.w;
    }
    for (; i < end; i++) {
        int s; float w;
        unpack_edge(g_edge[i], s, w);
        float4 v = *reinterpret_cast<const float4*>(y + (size_t)s * 64 + lane * 4);
        ax += w*v.x; ay += w*v.y; az += w*v.z; aw += w*v.w;
    }

    float invd = 1.0f / fmaxf((float)(end - beg), 1.0f);
    float4 r4 = *reinterpret_cast<const float4*>(r + (size_t)node * 64 + lane * 4);
    float4 b4 = *reinterpret_cast<const float4*>(bias + lane * 4);
    float4 o;
    o.x = ax * invd + b4.x + r4.x;
    o.y = ay * invd + b4.y + r4.y;
    o.z = az * invd + b4.z + r4.z;
    o.w = aw * invd + b4.w + r4.w;
    if (RELU) {
        o.x = fmaxf(o.x, 0.f); o.y = fmaxf(o.y, 0.f);
        o.z = fmaxf(o.z, 0.f); o.w = fmaxf(o.w, 0.f);
    }
    *reinterpret_cast<float4*>(out + (size_t)node * 64 + lane * 4) = o;
}

// ---------------- f32x2 row-pair GEMM, 8x8 per thread, double-buffered ------------
// Accumulators pack ROW pairs: acc[p][j] = (out[2p][j], out[2p+1][j]) for this
// thread's 8 rows x 8 cols. A read as natural row-pairs from smem (no dup);
// B duplicated into (b,b) u64 in registers (1 mov/col). B smem rows are skewed
// (16B gap every 32 floats) to cut LDS.128 bank conflicts to the dedup minimum.

#define FMA2(d, a, b) asm("fma.rn.f32x2 %0, %1, %2, %0;" : "+l"(d) : "l"(a), "l"(b))
#define DUP2(d, s)    asm("mov.b64 %0, {%1, %1};" : "=l"(d) : "f"(s))

__device__ __forceinline__ float2 u64_as_f2(u64 v) {
    float2 f;
    memcpy(&f, &v, 8);
    return f;
}

__device__ __forceinline__ int wskew(int c) { return c + 4 * (c >> 5); }

__global__ void __launch_bounds__(256, 2)
gemm2x_kernel(const float* __restrict__ A,
              const float* __restrict__ W0, const float* __restrict__ W1,
              float* __restrict__ out0, float* __restrict__ out1,
              int split, int n) {
    constexpr int BM = 128, K = 128, KC = 8;
    constexpr int NCHUNK = K / KC;     // 16
    constexpr int APAD = BM + 4;       // 132 floats per k-row (natural A)
    constexpr int WPAD = 144;          // 128 + 3 skew gaps (139) padded to 144

    __shared__ __align__(16) float As[2][KC][APAD];
    __shared__ __align__(16) float Ws[2][KC][WPAD];

    int row0 = blockIdx.x * BM;
    int col0 = blockIdx.y * 128;
    int tid = threadIdx.x;
    int tx = tid & 15;                 // col group: cols 8*tx .. +7
    int ty = tid >> 4;                 // row group: rows 8*ty .. +7

    // staging coords: thread stages row (tid>>1) of A and col (tid>>1) of W,
    // k-halves selected by tid&1 (one float4 of each per chunk).
    int srow = tid >> 1;
    int sk4  = (tid & 1) * 4;
    const float* Arow = A + (size_t)(row0 + srow) * K + sk4;
    bool a_ok = (row0 + srow) < n;
    int vc = col0 + srow;
    const float* Wrow = ((vc < split) ? (W0 + (size_t)vc * K)
                                      : (W1 + (size_t)(vc - split) * K)) + sk4;
    int wpos = wskew(srow);

    u64 acc[4][8];
#pragma unroll
    for (int p = 0; p < 4; p++)
#pragma unroll
        for (int j = 0; j < 8; j++) acc[p][j] = 0ull;

    float4 va = a_ok ? *reinterpret_cast<const float4*>(Arow) : make_float4(0.f, 0.f, 0.f, 0.f);
    float4 vw = *reinterpret_cast<const float4*>(Wrow);
    {
        As[0][sk4 + 0][srow] = va.x;
        As[0][sk4 + 1][srow] = va.y;
        As[0][sk4 + 2][srow] = va.z;
        As[0][sk4 + 3][srow] = va.w;
        Ws[0][sk4 + 0][wpos] = vw.x;
        Ws[0][sk4 + 1][wpos] = vw.y;
        Ws[0][sk4 + 2][wpos] = vw.z;
        Ws[0][sk4 + 3][wpos] = vw.w;
    }
    __syncthreads();

    int bpos = wskew(8 * tx);          // contiguous 8 floats (group never crosses a gap)

#pragma unroll
    for (int kc = 0; kc < NCHUNK; kc++) {
        int cur = kc & 1;
        if (kc < NCHUNK - 1) {
            int ko = (kc + 1) * KC;
            va = a_ok ? *reinterpret_cast<const float4*>(Arow + ko) : make_float4(0.f, 0.f, 0.f, 0.f);
            vw = *reinterpret_cast<const float4*>(Wrow + ko);
        }
#pragma unroll
        for (int k = 0; k < KC; k++) {
            // A: natural row-pairs, rows 8ty..8ty+7 (2 x LDS.128 = 4 u64)
            const ulonglong2* au = reinterpret_cast<const ulonglong2*>(&As[cur][k][8 * ty]);
            ulonglong2 a01 = au[0];
            ulonglong2 a23 = au[1];
            u64 ap[4] = {a01.x, a01.y, a23.x, a23.y};
            // B: 8 scalar cols (2 x LDS.128), duplicated into u64 in registers
            float4 b0 = *reinterpret_cast<const float4*>(&Ws[cur][k][bpos]);
            float4 b1 = *reinterpret_cast<const float4*>(&Ws[cur][k][bpos + 4]);
            u64 bd[8];
            DUP2(bd[0], b0.x); DUP2(bd[1], b0.y); DUP2(bd[2], b0.z); DUP2(bd[3], b0.w);
            DUP2(bd[4], b1.x); DUP2(bd[5], b1.y); DUP2(bd[6], b1.z); DUP2(bd[7], b1.w);
#pragma unroll
            for (int p = 0; p < 4; p++) {
#pragma unroll
                for (int j = 0; j < 8; j++)
                    FMA2(acc[p][j], ap[p], bd[j]);
            }
        }
        if (kc < NCHUNK - 1) {
            int nxt = cur ^ 1;
            As[nxt][sk4 + 0][srow] = va.x;
            As[nxt][sk4 + 1][srow] = va.y;
            As[nxt][sk4 + 2][srow] = va.z;
            As[nxt][sk4 + 3][srow] = va.w;
            Ws[nxt][sk4 + 0][wpos] = vw.x;
            Ws[nxt][sk4 + 1][wpos] = vw.y;
            Ws[nxt][sk4 + 2][wpos] = vw.z;
            Ws[nxt][sk4 + 3][wpos] = vw.w;
            __syncthreads();
        }
    }

    // ---- writeback: acc[p][j] holds rows (8ty+2p, 8ty+2p+1), col 8tx+j ----
    int vcBase = col0 + 8 * tx;        // 8-col group never straddles the split
    float* base = (vcBase < split) ? (out0 + vcBase) : (out1 + (vcBase - split));
#pragma unroll
    for (int p = 0; p < 4; p++) {
        int r0 = row0 + 8 * ty + 2 * p;
        float lo[8], hi[8];
#pragma unroll
        for (int j = 0; j < 8; j++) {
            float2 f = u64_as_f2(acc[p][j]);
            lo[j] = f.x;
            hi[j] = f.y;
        }
        if (r0 < n) {
            float* orow = base + (size_t)r0 * split;
            *reinterpret_cast<float4*>(orow + 0) = make_float4(lo[0], lo[1], lo[2], lo[3]);
            *reinterpret_cast<float4*>(orow + 4) = make_float4(lo[4], lo[5], lo[6], lo[7]);
        }
        if (r0 + 1 < n) {
            float* orow = base + (size_t)(r0 + 1) * split;
            *reinterpret_cast<float4*>(orow + 0) = make_float4(hi[0], hi[1], hi[2], hi[3]);
            *reinterpret_cast<float4*>(orow + 4) = make_float4(hi[4], hi[5], hi[6], hi[7]);
        }
    }
}

// ---------------- launch ----------------------------------------------------------
extern "C" void kernel_launch(void* const* d_in, const int* in_sizes, int n_in,
                              void* d_out, int out_size) {
    const float* x    = (const float*)d_in[0];
    const int*   ei   = (const int*)  d_in[1];
    const float* ew   = (const float*)d_in[2];
    // d_in[3] = node_type (unused by the reference)
    const float* W_l1 = (const float*)d_in[4];
    const float* b_l1 = (const float*)d_in[5];
    const float* W_r1 = (const float*)d_in[6];
    const float* W_l2 = (const float*)d_in[7];
    const float* b_l2 = (const float*)d_in[8];
    const float* W_r2 = (const float*)d_in[9];
    float* out = (float*)d_out;

    const int* src = ei;
    const int* dst = ei + N_EDGES;

    float *y1, *r1, *h, *y2, *r2;
    cudaGetSymbolAddress((void**)&y1, g_y1);
    cudaGetSymbolAddress((void**)&r1, g_r1);
    cudaGetSymbolAddress((void**)&h,  g_h);
    cudaGetSymbolAddress((void**)&y2, g_y2);
    cudaGetSymbolAddress((void**)&r2, g_r2);

    const int GB = (N_NODES + 127) / 128;           // 391

    // --- CSR build: ONE launch (zero + hist + scan + scatter, grid barrier) ---
    csr_kernel<<<CSR_BLOCKS, CSR_THREADS>>>(src, dst, ew);

    // --- layer 1: [W_l1; W_r1] stacked GEMM, gather-mean + fused epilogue ---
    gemm2x_kernel<<<dim3(GB, 2), 256>>>(x, W_l1, W_r1, y1, r1, 128, N_NODES);
    gather128_kernel<true><<<(N_NODES * 32 + 255) / 256, 256>>>(y1, r1, b_l1, h);

    // --- layer 2: [W_l2; W_r2] stacked GEMM (project to 64 before aggregating) ---
    gemm2x_kernel<<<dim3(GB, 1), 256>>>(h, W_l2, W_r2, y2, r2, 64, N_NODES);
    gather64_kernel<false><<<(N_NODES * 16 + 255) / 256, 256>>>(y2, r2, b_l2, out);
}

// round 8
// speedup vs baseline: 1.8668x; 1.0725x over previous
#include <cuda_runtime.h>
#include <cstddef>
#include <cstring>
#include <cstdint>

#define N_NODES 50000
#define N_EDGES 800000
#define IN_C 128
#define HID_C 128
#define OUT_C 64
#define CSR_BLOCKS 148
#define CSR_THREADS 1024
#define CSR_CHUNK 338          // 148*338 = 50024 >= N_NODES

typedef unsigned long long u64;

// ---------------- scratch (device globals: allocation-free rule) ----------------
__device__ int      g_cnt [N_NODES];
__device__ int      g_btot[CSR_BLOCKS];
__device__ int      g_rowptr[N_NODES + 1];
__device__ int      g_wp  [N_NODES];
__device__ u64      g_edge[N_EDGES];                    // packed (src, w)
__device__ unsigned g_bar;                              // monotonic grid-barrier ticket
__device__ __align__(16) float g_y1[N_NODES * HID_C];   // x @ W_l1^T
__device__ __align__(16) float g_r1[N_NODES * HID_C];   // x @ W_r1^T
__device__ __align__(16) float g_h [N_NODES * HID_C];   // layer-1 output
__device__ __align__(16) float g_y2[N_NODES * OUT_C];   // h @ W_l2^T
__device__ __align__(16) float g_r2[N_NODES * OUT_C];   // h @ W_r2^T

// ---------------- grid barrier (monotonic ticket: replay-safe, no reset) ---------
__device__ __forceinline__ void grid_bar() {
    __shared__ unsigned target;
    __syncthreads();
    if (threadIdx.x == 0) {
        __threadfence();
        unsigned t = atomicAdd(&g_bar, 1u);
        target = (t / CSR_BLOCKS + 1u) * CSR_BLOCKS;
        while (atomicAdd(&g_bar, 0u) < target) { }
        __threadfence();
    }
    __syncthreads();
}

// ---------------- single-launch CSR build (zero + hist + scan + scatter) ---------
__global__ void __launch_bounds__(CSR_THREADS)
csr_kernel(const int* __restrict__ src, const int* __restrict__ dst,
           const float* __restrict__ ew) {
    const int t = threadIdx.x;
    const int b = blockIdx.x;
    const int gt = b * CSR_THREADS + t;
    const int G = CSR_BLOCKS * CSR_THREADS;
    const int lane = t & 31;
    const int wid = t >> 5;
    __shared__ int wsum[32];
    __shared__ int s_boff;

    for (int i = gt; i < N_NODES; i += G) g_cnt[i] = 0;
    grid_bar();

    for (int e = gt; e < N_EDGES; e += G) atomicAdd(&g_cnt[dst[e]], 1);
    grid_bar();

    const int base = b * CSR_CHUNK;
    const int node = base + t;
    int v = 0;
    if (t < CSR_CHUNK && node < N_NODES) v = __ldcg(&g_cnt[node]);

    int inc = v;
#pragma unroll
    for (int off = 1; off < 32; off <<= 1) {
        int u = __shfl_up_sync(0xffffffffu, inc, off);
        if (lane >= off) inc += u;
    }
    if (lane == 31) wsum[wid] = inc;
    __syncthreads();
    if (wid == 0) {
        int wv = wsum[lane];
        int wi = wv;
#pragma unroll
        for (int off = 1; off < 32; off <<= 1) {
            int u = __shfl_up_sync(0xffffffffu, wi, off);
            if (lane >= off) wi += u;
        }
        wsum[lane] = wi;
    }
    __syncthreads();
    int ex = inc - v + ((wid > 0) ? wsum[wid - 1] : 0);
    int btot = wsum[31];
    if (t == 0) g_btot[b] = btot;
    __threadfence();
    grid_bar();

    {
        int contrib = (t < b) ? __ldcg(&g_btot[t]) : 0;
        int r = contrib;
#pragma unroll
        for (int off = 16; off > 0; off >>= 1) r += __shfl_down_sync(0xffffffffu, r, off);
        if (lane == 0) wsum[wid] = r;
        __syncthreads();
        if (wid == 0) {
            int r2 = wsum[lane];
#pragma unroll
            for (int off = 16; off > 0; off >>= 1) r2 += __shfl_down_sync(0xffffffffu, r2, off);
            if (lane == 0) s_boff = r2;
        }
        __syncthreads();
    }
    if (t < CSR_CHUNK && node < N_NODES) {
        int rp = s_boff + ex;
        g_rowptr[node] = rp;
        g_wp[node] = rp;
    }
    if (b == 0 && t == 0) g_rowptr[N_NODES] = N_EDGES;
    __threadfence();
    grid_bar();

    for (int e = gt; e < N_EDGES; e += G) {
        int d = dst[e];
        int pos = atomicAdd(&g_wp[d], 1);
        u64 rec = ((u64)__float_as_uint(ew[e]) << 32) | (unsigned)src[e];
        g_edge[pos] = rec;
    }
}

// ---------------- gather aggregation + fused SAGE epilogue ------------------------
__device__ __forceinline__ void unpack_edge(u64 rec, int& s, float& w) {
    s = (int)(unsigned)rec;
    w = __uint_as_float((unsigned)(rec >> 32));
}

template <bool RELU>
__global__ void __launch_bounds__(256)
gather128_kernel(const float* __restrict__ y, const float* __restrict__ r,
                 const float* __restrict__ bias, float* __restrict__ out) {
    int gt = blockIdx.x * blockDim.x + threadIdx.x;
    int node = gt >> 5;
    if (node >= N_NODES) return;
    int lane = threadIdx.x & 31;

    int beg = g_rowptr[node];
    int end = g_rowptr[node + 1];

    float ax = 0.f, ay = 0.f, az = 0.f, aw = 0.f;
    int i = beg;
    for (; i + 4 <= end; i += 4) {
        int s0, s1, s2, s3; float w0, w1, w2, w3;
        unpack_edge(g_edge[i],   s0, w0);
        unpack_edge(g_edge[i+1], s1, w1);
        unpack_edge(g_edge[i+2], s2, w2);
        unpack_edge(g_edge[i+3], s3, w3);
        float4 v0 = *reinterpret_cast<const float4*>(y + (size_t)s0 * 128 + lane * 4);
        float4 v1 = *reinterpret_cast<const float4*>(y + (size_t)s1 * 128 + lane * 4);
        float4 v2 = *reinterpret_cast<const float4*>(y + (size_t)s2 * 128 + lane * 4);
        float4 v3 = *reinterpret_cast<const float4*>(y + (size_t)s3 * 128 + lane * 4);
        ax += w0*v0.x + w1*v1.x + w2*v2.x + w3*v3.x;
        ay += w0*v0.y + w1*v1.y + w2*v2.y + w3*v3.y;
        az += w0*v0.z + w1*v1.z + w2*v2.z + w3*v3.z;
        aw += w0*v0.w + w1*v1.w + w2*v2.w + w3*v3.w;
    }
    for (; i < end; i++) {
        int s; float w;
        unpack_edge(g_edge[i], s, w);
        float4 v = *reinterpret_cast<const float4*>(y + (size_t)s * 128 + lane * 4);
        ax += w*v.x; ay += w*v.y; az += w*v.z; aw += w*v.w;
    }

    float invd = 1.0f / fmaxf((float)(end - beg), 1.0f);
    float4 r4 = *reinterpret_cast<const float4*>(r + (size_t)node * 128 + lane * 4);
    float4 b4 = *reinterpret_cast<const float4*>(bias + lane * 4);
    float4 o;
    o.x = ax * invd + b4.x + r4.x;
    o.y = ay * invd + b4.y + r4.y;
    o.z = az * invd + b4.z + r4.z;
    o.w = aw * invd + b4.w + r4.w;
    if (RELU) {
        o.x = fmaxf(o.x, 0.f); o.y = fmaxf(o.y, 0.f);
        o.z = fmaxf(o.z, 0.f); o.w = fmaxf(o.w, 0.f);
    }
    *reinterpret_cast<float4*>(out + (size_t)node * 128 + lane * 4) = o;
}

template <bool RELU>
__global__ void __launch_bounds__(256)
gather64_kernel(const float* __restrict__ y, const float* __restrict__ r,
                const float* __restrict__ bias, float* __restrict__ out) {
    int gt = blockIdx.x * blockDim.x + threadIdx.x;
    int node = gt >> 4;
    if (node >= N_NODES) return;
    int lane = threadIdx.x & 15;

    int beg = g_rowptr[node];
    int end = g_rowptr[node + 1];

    float ax = 0.f, ay = 0.f, az = 0.f, aw = 0.f;
    int i = beg;
    for (; i + 4 <= end; i += 4) {
        int s0, s1, s2, s3; float w0, w1, w2, w3;
        unpack_edge(g_edge[i],   s0, w0);
        unpack_edge(g_edge[i+1], s1, w1);
        unpack_edge(g_edge[i+2], s2, w2);
        unpack_edge(g_edge[i+3], s3, w3);
        float4 v0 = *reinterpret_cast<const float4*>(y + (size_t)s0 * 64 + lane * 4);
        float4 v1 = *reinterpret_cast<const float4*>(y + (size_t)s1 * 64 + lane * 4);
        float4 v2 = *reinterpret_cast<const float4*>(y + (size_t)s2 * 64 + lane * 4);
        float4 v3 = *reinterpret_cast<const float4*>(y + (size_t)s3 * 64 + lane * 4);
        ax += w0*v0.x + w1*v1.x + w2*v2.x + w3*v3.x;
        ay += w0*v0.y + w1*v1.y + w2*v2.y + w3*v3.y;
        az += w0*v0.z + w1*v1.z + w2*v2.z + w3*v3.z;
        aw += w0*v0.w + w1*v1.w + w2*v2.w + w3*v3.w;
    }
    for (; i < end; i++) {
        int s; float w;
        unpack_edge(g_edge[i], s, w);
        float4 v = *reinterpret_cast<const float4*>(y + (size_t)s * 64 + lane * 4);
        ax += w*v.x; ay += w*v.y; az += w*v.z; aw += w*v.w;
    }

    float invd = 1.0f / fmaxf((float)(end - beg), 1.0f);
    float4 r4 = *reinterpret_cast<const float4*>(r + (size_t)node * 64 + lane * 4);
    float4 b4 = *reinterpret_cast<const float4*>(bias + lane * 4);
    float4 o;
    o.x = ax * invd + b4.x + r4.x;
    o.y = ay * invd + b4.y + r4.y;
    o.z = az * invd + b4.z + r4.z;
    o.w = aw * invd + b4.w + r4.w;
    if (RELU) {
        o.x = fmaxf(o.x, 0.f); o.y = fmaxf(o.y, 0.f);
        o.z = fmaxf(o.z, 0.f); o.w = fmaxf(o.w, 0.f);
    }
    *reinterpret_cast<float4*>(out + (size_t)node * 64 + lane * 4) = o;
}

// ================= mma.sync tf32 GEMM (3-term split, fp32-class accuracy) =========
// D[128x128] = A[128x128] @ Wvirt[128x128]^T per CTA (Wvirt = [W0;W1] stacked).
// 8 warps, warp tile 64x32 via m16n8k8 (4 m-tiles x 4 n-tiles).
// A/W staged per KC=32 chunk as PRE-SPLIT tf32 hi/lo, row stride 36 (conflict-free).
// 3 terms per k-step: hi*hi + hi*lo + lo*hi. Error ~2^-21.

#define GSTRIDE 36
#define SA_HI 0
#define SA_LO (128 * GSTRIDE)
#define SW_HI (2 * 128 * GSTRIDE)
#define SW_LO (3 * 128 * GSTRIDE)
#define GSM_TOT (4 * 128 * GSTRIDE * 4)   // bytes = 73728

__device__ __forceinline__ void tf32_split(float x, float& hi, float& lo) {
    uint32_t h;
    asm("cvt.rna.tf32.f32 %0, %1;" : "=r"(h) : "f"(x));
    hi = __uint_as_float(h);
    float lf = x - hi;
    uint32_t l;
    asm("cvt.rna.tf32.f32 %0, %1;" : "=r"(l) : "f"(lf));
    lo = __uint_as_float(l);
}

__device__ __forceinline__ void mma_tf32(float* d, const uint32_t* a, const uint32_t* b) {
    asm volatile(
        "mma.sync.aligned.m16n8k8.row.col.f32.tf32.tf32.f32 "
        "{%0,%1,%2,%3}, {%4,%5,%6,%7}, {%8,%9}, {%0,%1,%2,%3};"
        : "+f"(d[0]), "+f"(d[1]), "+f"(d[2]), "+f"(d[3])
        : "r"(a[0]), "r"(a[1]), "r"(a[2]), "r"(a[3]), "r"(b[0]), "r"(b[1]));
}

__global__ void __launch_bounds__(256, 2)
gemm_mma_kernel(const float* __restrict__ A,
                const float* __restrict__ W0, const float* __restrict__ W1,
                float* __restrict__ out0, float* __restrict__ out1,
                int split, int n) {
    extern __shared__ __align__(16) float sm[];
    const int tid = threadIdx.x;
    const int wid = tid >> 5;
    const int lane = tid & 31;
    const int g = lane >> 2;            // 0..7
    const int tg = lane & 3;            // 0..3
    const int row0 = blockIdx.x * 128;
    const int col0 = blockIdx.y * 128;
    const int warp_m = (wid & 1) * 64;  // 2 m-groups of 64
    const int warp_n = (wid >> 1) * 32; // 4 n-groups of 32

    // staging coords: thread stages A row f>>3 and W vcol f>>3, float4 f&7
    float acc[4][4][4];
#pragma unroll
    for (int t = 0; t < 4; t++)
#pragma unroll
        for (int u = 0; u < 4; u++)
#pragma unroll
            for (int q = 0; q < 4; q++) acc[t][u][q] = 0.f;

    for (int kc = 0; kc < 4; kc++) {
        // ---- stage 32-wide K chunk of A and Wvirt as tf32 hi/lo ----
        __syncthreads();
#pragma unroll
        for (int i = 0; i < 4; i++) {
            int f = (i << 8) + tid;          // 0..1023
            int row = f >> 3;                // 0..127
            int c4 = f & 7;
            int sidx = row * GSTRIDE + c4 * 4;
            // A
            float4 av = make_float4(0.f, 0.f, 0.f, 0.f);
            if (row0 + row < n)
                av = *reinterpret_cast<const float4*>(A + (size_t)(row0 + row) * 128 + kc * 32 + c4 * 4);
            float4 ah, al;
            tf32_split(av.x, ah.x, al.x); tf32_split(av.y, ah.y, al.y);
            tf32_split(av.z, ah.z, al.z); tf32_split(av.w, ah.w, al.w);
            *reinterpret_cast<float4*>(&sm[SA_HI + sidx]) = ah;
            *reinterpret_cast<float4*>(&sm[SA_LO + sidx]) = al;
            // W
            int vcw = col0 + row;
            const float* wr = (vcw < split) ? (W0 + (size_t)vcw * 128)
                                            : (W1 + (size_t)(vcw - split) * 128);
            float4 wv = *reinterpret_cast<const float4*>(wr + kc * 32 + c4 * 4);
            float4 wh, wl;
            tf32_split(wv.x, wh.x, wl.x); tf32_split(wv.y, wh.y, wl.y);
            tf32_split(wv.z, wh.z, wl.z); tf32_split(wv.w, wh.w, wl.w);
            *reinterpret_cast<float4*>(&sm[SW_HI + sidx]) = wh;
            *reinterpret_cast<float4*>(&sm[SW_LO + sidx]) = wl;
        }
        __syncthreads();

        // ---- 4 k-steps of 8 ----
#pragma unroll
        for (int ks = 0; ks < 4; ks++) {
            int k0 = ks * 8;
            uint32_t Af[16], Bf[8], B2[8];
            // A hi fragments
#pragma unroll
            for (int t = 0; t < 4; t++) {
                int r = warp_m + 16 * t + g;
                Af[4*t+0] = __float_as_uint(sm[SA_HI + r * GSTRIDE + k0 + tg]);
                Af[4*t+1] = __float_as_uint(sm[SA_HI + (r + 8) * GSTRIDE + k0 + tg]);
                Af[4*t+2] = __float_as_uint(sm[SA_HI + r * GSTRIDE + k0 + tg + 4]);
                Af[4*t+3] = __float_as_uint(sm[SA_HI + (r + 8) * GSTRIDE + k0 + tg + 4]);
            }
            // B hi fragments
#pragma unroll
            for (int u = 0; u < 4; u++) {
                int nn = warp_n + 8 * u + g;
                Bf[2*u+0] = __float_as_uint(sm[SW_HI + nn * GSTRIDE + k0 + tg]);
                Bf[2*u+1] = __float_as_uint(sm[SW_HI + nn * GSTRIDE + k0 + tg + 4]);
            }
            // term 1: hi * hi
#pragma unroll
            for (int t = 0; t < 4; t++)
#pragma unroll
                for (int u = 0; u < 4; u++)
                    mma_tf32(acc[t][u], &Af[4*t], &Bf[2*u]);
            // B lo fragments; term 2: hi * lo
#pragma unroll
            for (int u = 0; u < 4; u++) {
                int nn = warp_n + 8 * u + g;
                B2[2*u+0] = __float_as_uint(sm[SW_LO + nn * GSTRIDE + k0 + tg]);
                B2[2*u+1] = __float_as_uint(sm[SW_LO + nn * GSTRIDE + k0 + tg + 4]);
            }
#pragma unroll
            for (int t = 0; t < 4; t++)
#pragma unroll
                for (int u = 0; u < 4; u++)
                    mma_tf32(acc[t][u], &Af[4*t], &B2[2*u]);
            // A lo fragments (reuse Af); term 3: lo * hi
#pragma unroll
            for (int t = 0; t < 4; t++) {
                int r = warp_m + 16 * t + g;
                Af[4*t+0] = __float_as_uint(sm[SA_LO + r * GSTRIDE + k0 + tg]);
                Af[4*t+1] = __float_as_uint(sm[SA_LO + (r + 8) * GSTRIDE + k0 + tg]);
                Af[4*t+2] = __float_as_uint(sm[SA_LO + r * GSTRIDE + k0 + tg + 4]);
                Af[4*t+3] = __float_as_uint(sm[SA_LO + (r + 8) * GSTRIDE + k0 + tg + 4]);
            }
#pragma unroll
            for (int t = 0; t < 4; t++)
#pragma unroll
                for (int u = 0; u < 4; u++)
                    mma_tf32(acc[t][u], &Af[4*t], &Bf[2*u]);
        }
    }

    // ---- writeback: c0,c1 -> (row, col 2tg), c2,c3 -> (row+8, col 2tg) ----
#pragma unroll
    for (int t = 0; t < 4; t++) {
        int r0 = row0 + warp_m + 16 * t + g;
        int r1 = r0 + 8;
#pragma unroll
        for (int u = 0; u < 4; u++) {
            int vc = col0 + warp_n + 8 * u + 2 * tg;
            float* dst0;
            if (vc < split) dst0 = out0 + vc;
            else            dst0 = out1 + (vc - split);
            if (r0 < n)
                *reinterpret_cast<float2*>(dst0 + (size_t)r0 * split) = make_float2(acc[t][u][0], acc[t][u][1]);
            if (r1 < n)
                *reinterpret_cast<float2*>(dst0 + (size_t)r1 * split) = make_float2(acc[t][u][2], acc[t][u][3]);
        }
    }
}

// ---------------- launch ----------------------------------------------------------
extern "C" void kernel_launch(void* const* d_in, const int* in_sizes, int n_in,
                              void* d_out, int out_size) {
    const float* x    = (const float*)d_in[0];
    const int*   ei   = (const int*)  d_in[1];
    const float* ew   = (const float*)d_in[2];
    // d_in[3] = node_type (unused by the reference)
    const float* W_l1 = (const float*)d_in[4];
    const float* b_l1 = (const float*)d_in[5];
    const float* W_r1 = (const float*)d_in[6];
    const float* W_l2 = (const float*)d_in[7];
    const float* b_l2 = (const float*)d_in[8];
    const float* W_r2 = (const float*)d_in[9];
    float* out = (float*)d_out;

    const int* src = ei;
    const int* dst = ei + N_EDGES;

    float *y1, *r1, *h, *y2, *r2;
    cudaGetSymbolAddress((void**)&y1, g_y1);
    cudaGetSymbolAddress((void**)&r1, g_r1);
    cudaGetSymbolAddress((void**)&h,  g_h);
    cudaGetSymbolAddress((void**)&y2, g_y2);
    cudaGetSymbolAddress((void**)&r2, g_r2);

    cudaFuncSetAttribute(gemm_mma_kernel, cudaFuncAttributeMaxDynamicSharedMemorySize, GSM_TOT);

    const int GB = (N_NODES + 127) / 128;           // 391

    // --- CSR build: ONE launch (zero + hist + scan + scatter, grid barrier) ---
    csr_kernel<<<CSR_BLOCKS, CSR_THREADS>>>(src, dst, ew);

    // --- layer 1: [W_l1 | W_r1] (256 virtual cols via gridDim.y), tf32 MMA GEMM ---
    gemm_mma_kernel<<<dim3(GB, 2), 256, GSM_TOT>>>(x, W_l1, W_r1, y1, r1, 128, N_NODES);
    gather128_kernel<true><<<(N_NODES * 32 + 255) / 256, 256>>>(y1, r1, b_l1, h);

    // --- layer 2: [W_l2; W_r2] stacked (128 virtual cols) ---
    gemm_mma_kernel<<<dim3(GB, 1), 256, GSM_TOT>>>(h, W_l2, W_r2, y2, r2, 64, N_NODES);
    gather64_kernel<false><<<(N_NODES * 16 + 255) / 256, 256>>>(y2, r2, b_l2, out);
}

// round 9
// speedup vs baseline: 2.2049x; 1.1811x over previous
#include <cuda_runtime.h>
#include <cuda_bf16.h>
#include <cstddef>
#include <cstring>
#include <cstdint>

#define N_NODES 50000
#define N_EDGES 800000
#define IN_C 128
#define HID_C 128
#define OUT_C 64
#define CSR_BLOCKS 148
#define CSR_THREADS 1024
#define CSR_CHUNK 338          // 148*338 = 50024 >= N_NODES

typedef unsigned long long u64;

// ---------------- scratch (device globals: allocation-free rule) ----------------
__device__ int      g_cnt [N_NODES];
__device__ int      g_btot[CSR_BLOCKS];
__device__ int      g_rowptr[N_NODES + 1];
__device__ int      g_wp  [N_NODES];
__device__ u64      g_edge[N_EDGES];                    // packed (src, w)
__device__ unsigned g_bar;                              // monotonic grid-barrier ticket
__device__ __align__(16) float g_y1[N_NODES * HID_C];   // x @ W_l1^T
__device__ __align__(16) float g_r1[N_NODES * HID_C];   // x @ W_r1^T
__device__ __align__(16) float g_h [N_NODES * HID_C];   // layer-1 output
__device__ __align__(16) float g_y2[N_NODES * OUT_C];   // h @ W_l2^T
__device__ __align__(16) float g_r2[N_NODES * OUT_C];   // h @ W_r2^T

// ---------------- grid barrier (monotonic ticket: replay-safe, no reset) ---------
__device__ __forceinline__ void grid_bar() {
    __shared__ unsigned target;
    __syncthreads();
    if (threadIdx.x == 0) {
        __threadfence();
        unsigned t = atomicAdd(&g_bar, 1u);
        target = (t / CSR_BLOCKS + 1u) * CSR_BLOCKS;
        while (atomicAdd(&g_bar, 0u) < target) { }
        __threadfence();
    }
    __syncthreads();
}

// ---------------- single-launch CSR build (zero + hist + scan + scatter) ---------
__global__ void __launch_bounds__(CSR_THREADS)
csr_kernel(const int* __restrict__ src, const int* __restrict__ dst,
           const float* __restrict__ ew) {
    const int t = threadIdx.x;
    const int b = blockIdx.x;
    const int gt = b * CSR_THREADS + t;
    const int G = CSR_BLOCKS * CSR_THREADS;
    const int lane = t & 31;
    const int wid = t >> 5;
    __shared__ int wsum[32];
    __shared__ int s_boff;

    for (int i = gt; i < N_NODES; i += G) g_cnt[i] = 0;
    grid_bar();

    for (int e = gt; e < N_EDGES; e += G) atomicAdd(&g_cnt[dst[e]], 1);
    grid_bar();

    const int base = b * CSR_CHUNK;
    const int node = base + t;
    int v = 0;
    if (t < CSR_CHUNK && node < N_NODES) v = __ldcg(&g_cnt[node]);

    int inc = v;
#pragma unroll
    for (int off = 1; off < 32; off <<= 1) {
        int u = __shfl_up_sync(0xffffffffu, inc, off);
        if (lane >= off) inc += u;
    }
    if (lane == 31) wsum[wid] = inc;
    __syncthreads();
    if (wid == 0) {
        int wv = wsum[lane];
        int wi = wv;
#pragma unroll
        for (int off = 1; off < 32; off <<= 1) {
            int u = __shfl_up_sync(0xffffffffu, wi, off);
            if (lane >= off) wi += u;
        }
        wsum[lane] = wi;
    }
    __syncthreads();
    int ex = inc - v + ((wid > 0) ? wsum[wid - 1] : 0);
    int btot = wsum[31];
    if (t == 0) g_btot[b] = btot;
    __threadfence();
    grid_bar();

    {
        int contrib = (t < b) ? __ldcg(&g_btot[t]) : 0;
        int r = contrib;
#pragma unroll
        for (int off = 16; off > 0; off >>= 1) r += __shfl_down_sync(0xffffffffu, r, off);
        if (lane == 0) wsum[wid] = r;
        __syncthreads();
        if (wid == 0) {
            int r2 = wsum[lane];
#pragma unroll
            for (int off = 16; off > 0; off >>= 1) r2 += __shfl_down_sync(0xffffffffu, r2, off);
            if (lane == 0) s_boff = r2;
        }
        __syncthreads();
    }
    if (t < CSR_CHUNK && node < N_NODES) {
        int rp = s_boff + ex;
        g_rowptr[node] = rp;
        g_wp[node] = rp;
    }
    if (b == 0 && t == 0) g_rowptr[N_NODES] = N_EDGES;
    __threadfence();
    grid_bar();

    for (int e = gt; e < N_EDGES; e += G) {
        int d = dst[e];
        int pos = atomicAdd(&g_wp[d], 1);
        u64 rec = ((u64)__float_as_uint(ew[e]) << 32) | (unsigned)src[e];
        g_edge[pos] = rec;
    }
}

// ---------------- gather aggregation + fused SAGE epilogue ------------------------
__device__ __forceinline__ void unpack_edge(u64 rec, int& s, float& w) {
    s = (int)(unsigned)rec;
    w = __uint_as_float((unsigned)(rec >> 32));
}

template <bool RELU>
__global__ void __launch_bounds__(256)
gather128_kernel(const float* __restrict__ y, const float* __restrict__ r,
                 const float* __restrict__ bias, float* __restrict__ out) {
    int gt = blockIdx.x * blockDim.x + threadIdx.x;
    int node = gt >> 5;
    if (node >= N_NODES) return;
    int lane = threadIdx.x & 31;

    int beg = g_rowptr[node];
    int end = g_rowptr[node + 1];

    float ax = 0.f, ay = 0.f, az = 0.f, aw = 0.f;
    int i = beg;
    for (; i + 4 <= end; i += 4) {
        int s0, s1, s2, s3; float w0, w1, w2, w3;
        unpack_edge(g_edge[i],   s0, w0);
        unpack_edge(g_edge[i+1], s1, w1);
        unpack_edge(g_edge[i+2], s2, w2);
        unpack_edge(g_edge[i+3], s3, w3);
        float4 v0 = *reinterpret_cast<const float4*>(y + (size_t)s0 * 128 + lane * 4);
        float4 v1 = *reinterpret_cast<const float4*>(y + (size_t)s1 * 128 + lane * 4);
        float4 v2 = *reinterpret_cast<const float4*>(y + (size_t)s2 * 128 + lane * 4);
        float4 v3 = *reinterpret_cast<const float4*>(y + (size_t)s3 * 128 + lane * 4);
        ax += w0*v0.x + w1*v1.x + w2*v2.x + w3*v3.x;
        ay += w0*v0.y + w1*v1.y + w2*v2.y + w3*v3.y;
        az += w0*v0.z + w1*v1.z + w2*v2.z + w3*v3.z;
        aw += w0*v0.w + w1*v1.w + w2*v2.w + w3*v3.w;
    }
    for (; i < end; i++) {
        int s; float w;
        unpack_edge(g_edge[i], s, w);
        float4 v = *reinterpret_cast<const float4*>(y + (size_t)s * 128 + lane * 4);
        ax += w*v.x; ay += w*v.y; az += w*v.z; aw += w*v.w;
    }

    float invd = 1.0f / fmaxf((float)(end - beg), 1.0f);
    float4 r4 = *reinterpret_cast<const float4*>(r + (size_t)node * 128 + lane * 4);
    float4 b4 = *reinterpret_cast<const float4*>(bias + lane * 4);
    float4 o;
    o.x = ax * invd + b4.x + r4.x;
    o.y = ay * invd + b4.y + r4.y;
    o.z = az * invd + b4.z + r4.z;
    o.w = aw * invd + b4.w + r4.w;
    if (RELU) {
        o.x = fmaxf(o.x, 0.f); o.y = fmaxf(o.y, 0.f);
        o.z = fmaxf(o.z, 0.f); o.w = fmaxf(o.w, 0.f);
    }
    *reinterpret_cast<float4*>(out + (size_t)node * 128 + lane * 4) = o;
}

template <bool RELU>
__global__ void __launch_bounds__(256)
gather64_kernel(const float* __restrict__ y, const float* __restrict__ r,
                const float* __restrict__ bias, float* __restrict__ out) {
    int gt = blockIdx.x * blockDim.x + threadIdx.x;
    int node = gt >> 4;
    if (node >= N_NODES) return;
    int lane = threadIdx.x & 15;

    int beg = g_rowptr[node];
    int end = g_rowptr[node + 1];

    float ax = 0.f, ay = 0.f, az = 0.f, aw = 0.f;
    int i = beg;
    for (; i + 4 <= end; i += 4) {
        int s0, s1, s2, s3; float w0, w1, w2, w3;
        unpack_edge(g_edge[i],   s0, w0);
        unpack_edge(g_edge[i+1], s1, w1);
        unpack_edge(g_edge[i+2], s2, w2);
        unpack_edge(g_edge[i+3], s3, w3);
        float4 v0 = *reinterpret_cast<const float4*>(y + (size_t)s0 * 64 + lane * 4);
        float4 v1 = *reinterpret_cast<const float4*>(y + (size_t)s1 * 64 + lane * 4);
        float4 v2 = *reinterpret_cast<const float4*>(y + (size_t)s2 * 64 + lane * 4);
        float4 v3 = *reinterpret_cast<const float4*>(y + (size_t)s3 * 64 + lane * 4);
        ax += w0*v0.x + w1*v1.x + w2*v2.x + w3*v3.x;
        ay += w0*v0.y + w1*v1.y + w2*v2.y + w3*v3.y;
        az += w0*v0.z + w1*v1.z + w2*v2.z + w3*v3.z;
        aw += w0*v0.w + w1*v1.w + w2*v2.w + w3*v3.w;
    }
    for (; i < end; i++) {
        int s; float w;
        unpack_edge(g_edge[i], s, w);
        float4 v = *reinterpret_cast<const float4*>(y + (size_t)s * 64 + lane * 4);
        ax += w*v.x; ay += w*v.y; az += w*v.z; aw += w*v.w;
    }

    float invd = 1.0f / fmaxf((float)(end - beg), 1.0f);
    float4 r4 = *reinterpret_cast<const float4*>(r + (size_t)node * 64 + lane * 4);
    float4 b4 = *reinterpret_cast<const float4*>(bias + lane * 4);
    float4 o;
    o.x = ax * invd + b4.x + r4.x;
    o.y = ay * invd + b4.y + r4.y;
    o.z = az * invd + b4.z + r4.z;
    o.w = aw * invd + b4.w + r4.w;
    if (RELU) {
        o.x = fmaxf(o.x, 0.f); o.y = fmaxf(o.y, 0.f);
        o.z = fmaxf(o.z, 0.f); o.w = fmaxf(o.w, 0.f);
    }
    *reinterpret_cast<float4*>(out + (size_t)node * 64 + lane * 4) = o;
}

// ================= mma.sync bf16 GEMM (3-term split) ==============================
// D[128x128] = A[128x128] @ Wvirt[128x128]^T per CTA (Wvirt = [W0;W1] stacked).
// 8 warps, warp tile 64x32 via m16n8k16 (4 m-tiles x 4 n-tiles).
// A/W staged per KC=32 chunk as PRE-SPLIT bf16 hi/lo pairs (packed bf16x2 words),
// row stride 20 words (conflict-free: (20g+tg) mod 32 is a permutation).
// 3 terms per k-step: hi*hi + hi*lo + lo*hi. Error ~2^-16 per product.

#define GSTRIDE 20                       // words per row (16 data + 4 pad)
#define SA_HI 0
#define SA_LO (128 * GSTRIDE)
#define SW_HI (2 * 128 * GSTRIDE)
#define SW_LO (3 * 128 * GSTRIDE)
#define GSM_TOT (4 * 128 * GSTRIDE * 4)  // 40960 bytes

__device__ __forceinline__ uint32_t pack_bf16x2(float lo, float hi) {
    uint32_t r;
    asm("cvt.rn.bf16x2.f32 %0, %1, %2;" : "=r"(r) : "f"(hi), "f"(lo));
    return r;
}

__device__ __forceinline__ void bsplit(float x, float& hf, float& lf) {
    __nv_bfloat16 bh = __float2bfloat16(x);
    hf = __bfloat162float(bh);
    lf = x - hf;
}

__device__ __forceinline__ void mma_bf16(float* d, const uint32_t* a, const uint32_t* b) {
    asm volatile(
        "mma.sync.aligned.m16n8k16.row.col.f32.bf16.bf16.f32 "
        "{%0,%1,%2,%3}, {%4,%5,%6,%7}, {%8,%9}, {%0,%1,%2,%3};"
        : "+f"(d[0]), "+f"(d[1]), "+f"(d[2]), "+f"(d[3])
        : "r"(a[0]), "r"(a[1]), "r"(a[2]), "r"(a[3]), "r"(b[0]), "r"(b[1]));
}

__global__ void __launch_bounds__(256, 2)
gemm_mma_kernel(const float* __restrict__ A,
                const float* __restrict__ W0, const float* __restrict__ W1,
                float* __restrict__ out0, float* __restrict__ out1,
                int split, int n) {
    extern __shared__ __align__(16) uint32_t smu[];
    const int tid = threadIdx.x;
    const int wid = tid >> 5;
    const int lane = tid & 31;
    const int g = lane >> 2;            // 0..7
    const int tg = lane & 3;            // 0..3
    const int row0 = blockIdx.x * 128;
    const int col0 = blockIdx.y * 128;
    const int warp_m = (wid & 1) * 64;  // 2 m-groups of 64
    const int warp_n = (wid >> 1) * 32; // 4 n-groups of 32

    float acc[4][4][4];
#pragma unroll
    for (int t = 0; t < 4; t++)
#pragma unroll
        for (int u = 0; u < 4; u++)
#pragma unroll
            for (int q = 0; q < 4; q++) acc[t][u][q] = 0.f;

    for (int kc = 0; kc < 4; kc++) {
        // ---- stage 32-wide K chunk of A and Wvirt as bf16 hi/lo pairs ----
        __syncthreads();
#pragma unroll
        for (int i = 0; i < 4; i++) {
            int f = (i << 8) + tid;          // 0..1023
            int row = f >> 3;                // 0..127
            int c4 = f & 7;                  // float4 index within 32-col chunk
            int widx = row * GSTRIDE + c4 * 2;
            // A
            float4 av = make_float4(0.f, 0.f, 0.f, 0.f);
            if (row0 + row < n)
                av = *reinterpret_cast<const float4*>(A + (size_t)(row0 + row) * 128 + kc * 32 + c4 * 4);
            float h0, h1, h2, h3, l0, l1, l2, l3;
            bsplit(av.x, h0, l0); bsplit(av.y, h1, l1);
            bsplit(av.z, h2, l2); bsplit(av.w, h3, l3);
            *reinterpret_cast<uint2*>(&smu[SA_HI + widx]) =
                make_uint2(pack_bf16x2(h0, h1), pack_bf16x2(h2, h3));
            *reinterpret_cast<uint2*>(&smu[SA_LO + widx]) =
                make_uint2(pack_bf16x2(l0, l1), pack_bf16x2(l2, l3));
            // W
            int vcw = col0 + row;
            const float* wr = (vcw < split) ? (W0 + (size_t)vcw * 128)
                                            : (W1 + (size_t)(vcw - split) * 128);
            float4 wv = *reinterpret_cast<const float4*>(wr + kc * 32 + c4 * 4);
            bsplit(wv.x, h0, l0); bsplit(wv.y, h1, l1);
            bsplit(wv.z, h2, l2); bsplit(wv.w, h3, l3);
            *reinterpret_cast<uint2*>(&smu[SW_HI + widx]) =
                make_uint2(pack_bf16x2(h0, h1), pack_bf16x2(h2, h3));
            *reinterpret_cast<uint2*>(&smu[SW_LO + widx]) =
                make_uint2(pack_bf16x2(l0, l1), pack_bf16x2(l2, l3));
        }
        __syncthreads();

        // ---- 2 k-steps of 16 ----
#pragma unroll
        for (int ks = 0; ks < 2; ks++) {
            int pb = ks * 8 + tg;            // bf16-pair (word) index base
            uint32_t Af[16], Bf[8], B2[8];
            // A hi fragments: a0=(r,pb) a1=(r+8,pb) a2=(r,pb+4) a3=(r+8,pb+4)
#pragma unroll
            for (int t = 0; t < 4; t++) {
                int r = warp_m + 16 * t + g;
                Af[4*t+0] = smu[SA_HI + r * GSTRIDE + pb];
                Af[4*t+1] = smu[SA_HI + (r + 8) * GSTRIDE + pb];
                Af[4*t+2] = smu[SA_HI + r * GSTRIDE + pb + 4];
                Af[4*t+3] = smu[SA_HI + (r + 8) * GSTRIDE + pb + 4];
            }
            // B hi fragments: b0=(n,pb) b1=(n,pb+4)
#pragma unroll
            for (int u = 0; u < 4; u++) {
                int nn = warp_n + 8 * u + g;
                Bf[2*u+0] = smu[SW_HI + nn * GSTRIDE + pb];
                Bf[2*u+1] = smu[SW_HI + nn * GSTRIDE + pb + 4];
            }
            // term 1: hi * hi
#pragma unroll
            for (int t = 0; t < 4; t++)
#pragma unroll
                for (int u = 0; u < 4; u++)
                    mma_bf16(acc[t][u], &Af[4*t], &Bf[2*u]);
            // B lo; term 2: hi * lo
#pragma unroll
            for (int u = 0; u < 4; u++) {
                int nn = warp_n + 8 * u + g;
                B2[2*u+0] = smu[SW_LO + nn * GSTRIDE + pb];
                B2[2*u+1] = smu[SW_LO + nn * GSTRIDE + pb + 4];
            }
#pragma unroll
            for (int t = 0; t < 4; t++)
#pragma unroll
                for (int u = 0; u < 4; u++)
                    mma_bf16(acc[t][u], &Af[4*t], &B2[2*u]);
            // A lo (reuse Af); term 3: lo * hi
#pragma unroll
            for (int t = 0; t < 4; t++) {
                int r = warp_m + 16 * t + g;
                Af[4*t+0] = smu[SA_LO + r * GSTRIDE + pb];
                Af[4*t+1] = smu[SA_LO + (r + 8) * GSTRIDE + pb];
                Af[4*t+2] = smu[SA_LO + r * GSTRIDE + pb + 4];
                Af[4*t+3] = smu[SA_LO + (r + 8) * GSTRIDE + pb + 4];
            }
#pragma unroll
            for (int t = 0; t < 4; t++)
#pragma unroll
                for (int u = 0; u < 4; u++)
                    mma_bf16(acc[t][u], &Af[4*t], &Bf[2*u]);
        }
    }

    // ---- writeback: c0,c1 -> (row, col 2tg), c2,c3 -> (row+8, col 2tg) ----
#pragma unroll
    for (int t = 0; t < 4; t++) {
        int r0 = row0 + warp_m + 16 * t + g;
        int r1 = r0 + 8;
#pragma unroll
        for (int u = 0; u < 4; u++) {
            int vc = col0 + warp_n + 8 * u + 2 * tg;
            float* dst0;
            if (vc < split) dst0 = out0 + vc;
            else            dst0 = out1 + (vc - split);
            if (r0 < n)
                *reinterpret_cast<float2*>(dst0 + (size_t)r0 * split) = make_float2(acc[t][u][0], acc[t][u][1]);
            if (r1 < n)
                *reinterpret_cast<float2*>(dst0 + (size_t)r1 * split) = make_float2(acc[t][u][2], acc[t][u][3]);
        }
    }
}

// ---------------- launch ----------------------------------------------------------
extern "C" void kernel_launch(void* const* d_in, const int* in_sizes, int n_in,
                              void* d_out, int out_size) {
    const float* x    = (const float*)d_in[0];
    const int*   ei   = (const int*)  d_in[1];
    const float* ew   = (const float*)d_in[2];
    // d_in[3] = node_type (unused by the reference)
    const float* W_l1 = (const float*)d_in[4];
    const float* b_l1 = (const float*)d_in[5];
    const float* W_r1 = (const float*)d_in[6];
    const float* W_l2 = (const float*)d_in[7];
    const float* b_l2 = (const float*)d_in[8];
    const float* W_r2 = (const float*)d_in[9];
    float* out = (float*)d_out;

    const int* src = ei;
    const int* dst = ei + N_EDGES;

    float *y1, *r1, *h, *y2, *r2;
    cudaGetSymbolAddress((void**)&y1, g_y1);
    cudaGetSymbolAddress((void**)&r1, g_r1);
    cudaGetSymbolAddress((void**)&h,  g_h);
    cudaGetSymbolAddress((void**)&y2, g_y2);
    cudaGetSymbolAddress((void**)&r2, g_r2);

    cudaFuncSetAttribute(gemm_mma_kernel, cudaFuncAttributeMaxDynamicSharedMemorySize, GSM_TOT);

    const int GB = (N_NODES + 127) / 128;           // 391

    // --- CSR build: ONE launch (zero + hist + scan + scatter, grid barrier) ---
    csr_kernel<<<CSR_BLOCKS, CSR_THREADS>>>(src, dst, ew);

    // --- layer 1: [W_l1 | W_r1] (256 virtual cols via gridDim.y), bf16 MMA GEMM ---
    gemm_mma_kernel<<<dim3(GB, 2), 256, GSM_TOT>>>(x, W_l1, W_r1, y1, r1, 128, N_NODES);
    gather128_kernel<true><<<(N_NODES * 32 + 255) / 256, 256>>>(y1, r1, b_l1, h);

    // --- layer 2: [W_l2; W_r2] stacked (128 virtual cols) ---
    gemm_mma_kernel<<<dim3(GB, 1), 256, GSM_TOT>>>(h, W_l2, W_r2, y2, r2, 64, N_NODES);
    gather64_kernel<false><<<(N_NODES * 16 + 255) / 256, 256>>>(y2, r2, b_l2, out);
}